// round 12
// baseline (speedup 1.0000x reference)
#include <cuda_runtime.h>
#include <cuda_bf16.h>
#include <cstdint>
#include <cstddef>

// ============================================================================
// Quantized FFN via exact integer-in-bf16 GEMMs:
//   out = quant_linear(relu(quant_linear(x, w1, b1)), w2, b2)
// R11: R10 fused-GEMM2 design with the quantA coverage bug fixed
// (it<8: all 64 rows of the A tile quantized; R10 left rows 32-63 poisoned).
// ============================================================================

#define EPSQ 1e-8f

static constexpr int M_TOT = 8192;
static constexpr int D_DIM = 1024;
static constexpr int F_DIM = 4096;
static constexpr int SGRID = 1184;

// ---------------- scratch ----------------------------------------------------
__device__ float g_maxx;
__device__ float g_maxh;
__device__ __nv_bfloat16 g_qx[(size_t)M_TOT * D_DIM];
__device__ __nv_bfloat16 g_qw1[(size_t)F_DIM * D_DIM];
__device__ float g_scale1[F_DIM];
__device__ float g_badd1[F_DIM];
__device__ __nv_bfloat16 g_qw2[(size_t)D_DIM * F_DIM];
__device__ float g_sw2[D_DIM];
__device__ float g_h[(size_t)M_TOT * F_DIM];

// ---------------- PTX helpers ------------------------------------------------
__device__ __forceinline__ uint32_t smem_u32(const void* p) {
    uint32_t a;
    asm("{ .reg .u64 t; cvta.to.shared.u64 t, %1; cvt.u32.u64 %0, t; }"
        : "=r"(a) : "l"(p));
    return a;
}

__device__ __forceinline__ void cp16(uint32_t dst, const void* src) {
    asm volatile("cp.async.cg.shared.global [%0], [%1], 16;" :: "r"(dst), "l"(src));
}
#define CP_COMMIT() asm volatile("cp.async.commit_group;" ::: "memory")
#define CP_WAIT1()  asm volatile("cp.async.wait_group 1;" ::: "memory")
#define CP_WAIT2()  asm volatile("cp.async.wait_group 2;" ::: "memory")

__device__ __forceinline__ void ldsm4(uint32_t* r, uint32_t addr) {
    asm volatile("ldmatrix.sync.aligned.m8n8.x4.shared.b16 {%0,%1,%2,%3}, [%4];"
        : "=r"(r[0]), "=r"(r[1]), "=r"(r[2]), "=r"(r[3]) : "r"(addr));
}

__device__ __forceinline__ void mma_bf16(float* c, const uint32_t* a, const uint32_t* b) {
    asm volatile(
        "mma.sync.aligned.m16n8k16.row.col.f32.bf16.bf16.f32 "
        "{%0,%1,%2,%3}, {%4,%5,%6,%7}, {%8,%9}, {%0,%1,%2,%3};"
        : "+f"(c[0]), "+f"(c[1]), "+f"(c[2]), "+f"(c[3])
        : "r"(a[0]), "r"(a[1]), "r"(a[2]), "r"(a[3]), "r"(b[0]), "r"(b[1]));
}

__device__ __forceinline__ float4 ldcs4(const float4* p) {
    float4 v;
    asm volatile("ld.global.cs.v4.f32 {%0,%1,%2,%3}, [%4];"
        : "=f"(v.x), "=f"(v.y), "=f"(v.z), "=f"(v.w) : "l"(p));
    return v;
}

__device__ __forceinline__ uint2 quant_pack4(float4 v, float rs, float lo, float hi) {
    float q0 = fminf(fmaxf(rintf(v.x * rs), lo), hi);
    float q1 = fminf(fmaxf(rintf(v.y * rs), lo), hi);
    float q2 = fminf(fmaxf(rintf(v.z * rs), lo), hi);
    float q3 = fminf(fmaxf(rintf(v.w * rs), lo), hi);
    __nv_bfloat162 l = __floats2bfloat162_rn(q0, q1);
    __nv_bfloat162 h = __floats2bfloat162_rn(q2, q3);
    uint2 pk;
    pk.x = *reinterpret_cast<unsigned int*>(&l);
    pk.y = *reinterpret_cast<unsigned int*>(&h);
    return pk;
}

// ---------------- elementwise / reduction kernels ----------------------------
__global__ void max_x_kernel(const float* __restrict__ x) {
    float m = 0.0f;
    const int n4 = (M_TOT * D_DIM) / 4;
    const int stride = gridDim.x * blockDim.x;
    int i = blockIdx.x * blockDim.x + threadIdx.x;
    #pragma unroll 4
    for (; i < n4; i += stride) {
        float4 v = reinterpret_cast<const float4*>(x)[i];
        m = fmaxf(m, fmaxf(fmaxf(v.x, v.y), fmaxf(v.z, v.w)));
    }
    #pragma unroll
    for (int o = 16; o; o >>= 1) m = fmaxf(m, __shfl_xor_sync(0xffffffffu, m, o));
    __shared__ float red[8];
    int wid = threadIdx.x >> 5, lid = threadIdx.x & 31;
    if (lid == 0) red[wid] = m;
    __syncthreads();
    if (threadIdx.x == 0) {
        float b = red[0];
        int nw = blockDim.x >> 5;
        for (int i2 = 1; i2 < nw; i2++) b = fmaxf(b, red[i2]);
        atomicMax(reinterpret_cast<unsigned int*>(&g_maxx), __float_as_uint(fmaxf(b, 0.0f)));
    }
}

template <int K, bool W1>
__global__ void quantw_fused(const float* __restrict__ w, const float* __restrict__ b1,
                             __nv_bfloat16* __restrict__ qw) {
    constexpr int NV = K / 1024;
    const int r = blockIdx.x;
    const int t = threadIdx.x;
    const float4* row = reinterpret_cast<const float4*>(w + (size_t)r * K);
    float4 v[NV];
    float m = 0.0f;
    #pragma unroll
    for (int i = 0; i < NV; ++i) {
        v[i] = ldcs4(row + t + i * 256);
        m = fmaxf(m, fmaxf(fmaxf(fabsf(v[i].x), fabsf(v[i].y)),
                           fmaxf(fabsf(v[i].z), fabsf(v[i].w))));
    }
    #pragma unroll
    for (int o = 16; o; o >>= 1) m = fmaxf(m, __shfl_xor_sync(0xffffffffu, m, o));
    __shared__ float red[8];
    __shared__ float rs_sh;
    if ((t & 31) == 0) red[t >> 5] = m;
    __syncthreads();
    if (t == 0) {
        float b = red[0];
        #pragma unroll
        for (int i = 1; i < 8; ++i) b = fmaxf(b, red[i]);
        float s = __fdiv_rn(fmaxf(b, EPSQ), 127.0f);
        rs_sh = __fdiv_rn(1.0f, s);
        if (W1) {
            float s1 = __fdiv_rn(fmaxf(g_maxx, EPSQ), 255.0f);
            float sc = s1 * s;
            g_scale1[r] = sc;
            g_badd1[r] = rintf(__fdiv_rn(b1[r], sc)) * sc;
        } else {
            g_sw2[r] = s;
        }
    }
    __syncthreads();
    const float rs = rs_sh;
    #pragma unroll
    for (int i = 0; i < NV; ++i)
        reinterpret_cast<uint2*>(qw)[((size_t)r * K) / 4 + t + i * 256] =
            quant_pack4(v[i], rs, -128.0f, 127.0f);
}

__global__ void quant_x_kernel(const float* __restrict__ x) {
    const float rs = __fdiv_rn(255.0f, fmaxf(g_maxx, EPSQ));
    const int n4 = (M_TOT * D_DIM) / 4;
    const int stride = gridDim.x * blockDim.x;
    int i = blockIdx.x * blockDim.x + threadIdx.x;
    #pragma unroll 4
    for (; i < n4; i += stride) {
        float4 v = ldcs4(reinterpret_cast<const float4*>(x) + i);
        reinterpret_cast<uint2*>(g_qx)[i] = quant_pack4(v, rs, 0.0f, 255.0f);
    }
}

// ---------------- GEMM1: qx (bf16) x qw1 -> h (f32) --------------------------
// CTA 128x256x64; 256 thr, 8 warps 2(M)x4(N), warp 64x64; 4-stage cp.async.
static constexpr int AST = 144;
static constexpr int NSTAGE1 = 4;
static constexpr int STAGEB1 = (128 + 256) * AST;       // 55296
static constexpr int SMEM1 = NSTAGE1 * STAGEB1;         // 221184

__global__ void __launch_bounds__(256, 1) gemm1_kernel()
{
    constexpr int ABYTES = 128 * AST;
    extern __shared__ __align__(16) unsigned char smem[];
    __shared__ float csc[256], cbd[256], wred[8];

    const int tid = threadIdx.x, lane = tid & 31, wid = tid >> 5;
    const int warp_m = wid & 1, warp_n = wid >> 1;
    const int m0 = blockIdx.y * 128, n0 = blockIdx.x * 256;

    {
        int n = n0 + tid;
        csc[tid] = g_scale1[n];
        cbd[tid] = g_badd1[n];
    }

    const uint32_t sAddr = smem_u32(smem);
    const int NT = D_DIM / 64;

    auto load_tile = [&](int t, int s) {
        const uint32_t sb = sAddr + s * STAGEB1;
        const int kb = t * 64;
        #pragma unroll
        for (int it = 0; it < 4; ++it) {
            int i = tid + it * 256;
            int r = i >> 3, ch = i & 7;
            cp16(sb + r * AST + ch * 16, g_qx + (size_t)(m0 + r) * D_DIM + kb + ch * 8);
        }
        #pragma unroll
        for (int it = 0; it < 8; ++it) {
            int i = tid + it * 256;
            int r = i >> 3, ch = i & 7;
            cp16(sb + ABYTES + r * AST + ch * 16,
                 g_qw1 + (size_t)(n0 + r) * D_DIM + kb + ch * 8);
        }
    };

    load_tile(0, 0); CP_COMMIT();
    load_tile(1, 1); CP_COMMIT();
    load_tile(2, 2); CP_COMMIT();

    float acc[4][8][4];
    #pragma unroll
    for (int i = 0; i < 4; ++i)
        #pragma unroll
        for (int j = 0; j < 8; ++j)
            #pragma unroll
            for (int k = 0; k < 4; ++k) acc[i][j][k] = 0.0f;

    const uint32_t aLane =
        (uint32_t)(warp_m * 64 + (lane & 15)) * AST + (lane >> 4) * 16;
    const uint32_t bLane = ABYTES +
        (uint32_t)(warp_n * 64 + ((lane & 7) | ((lane & 16) >> 1))) * AST +
        ((lane >> 3) & 1) * 16;

    int buf = 0;
    for (int t = 0; t < NT; ++t) {
        CP_WAIT2();
        __syncthreads();
        if (t + 3 < NT) {
            int s = buf + 3; if (s >= NSTAGE1) s -= NSTAGE1;
            load_tile(t + 3, s);
        }
        CP_COMMIT();

        const uint32_t base = sAddr + buf * STAGEB1;
        #pragma unroll
        for (int ks = 0; ks < 4; ++ks) {
            uint32_t af[4][4], bf[4][4];
            #pragma unroll
            for (int fm = 0; fm < 4; ++fm)
                ldsm4(af[fm], base + aLane + fm * (16 * AST) + ks * 32);
            #pragma unroll
            for (int fp = 0; fp < 4; ++fp)
                ldsm4(bf[fp], base + bLane + fp * (16 * AST) + ks * 32);
            #pragma unroll
            for (int fm = 0; fm < 4; ++fm)
                #pragma unroll
                for (int fn = 0; fn < 8; ++fn)
                    mma_bf16(acc[fm][fn], af[fm], &bf[fn >> 1][(fn & 1) * 2]);
        }
        if (++buf == NSTAGE1) buf = 0;
    }

    float lmax = 0.0f;
    #pragma unroll
    for (int fm = 0; fm < 4; ++fm) {
        const int r0 = m0 + warp_m * 64 + fm * 16 + (lane >> 2);
        #pragma unroll
        for (int fn = 0; fn < 8; ++fn) {
            const int cl = warp_n * 64 + fn * 8 + (lane & 3) * 2;
            const float s0 = csc[cl], s1 = csc[cl + 1];
            const float d0 = cbd[cl], d1 = cbd[cl + 1];
            float v00 = fmaxf(s0 * acc[fm][fn][0] + d0, 0.0f);
            float v01 = fmaxf(s1 * acc[fm][fn][1] + d1, 0.0f);
            float v10 = fmaxf(s0 * acc[fm][fn][2] + d0, 0.0f);
            float v11 = fmaxf(s1 * acc[fm][fn][3] + d1, 0.0f);
            lmax = fmaxf(lmax, fmaxf(fmaxf(v00, v01), fmaxf(v10, v11)));
            *reinterpret_cast<float2*>(g_h + (size_t)r0 * F_DIM + n0 + cl) =
                make_float2(v00, v01);
            *reinterpret_cast<float2*>(g_h + (size_t)(r0 + 8) * F_DIM + n0 + cl) =
                make_float2(v10, v11);
        }
    }

    #pragma unroll
    for (int o = 16; o; o >>= 1) lmax = fmaxf(lmax, __shfl_xor_sync(0xffffffffu, lmax, o));
    if (lane == 0) wred[wid] = lmax;
    __syncthreads();
    if (tid == 0) {
        float b = wred[0];
        #pragma unroll
        for (int i = 1; i < 8; i++) b = fmaxf(b, wred[i]);
        atomicMax(reinterpret_cast<unsigned int*>(&g_maxh), __float_as_uint(b));
    }
}

// ---------------- GEMM2: fused h-quant, qh x qw2 -> out ----------------------
// CTA 64x128x64; 128 thr, 4 warps 2(M)x2(N), warp 32x64; 2 CTAs/SM.
// Rings: B bf16 x3, A bf16 x2 (filled by in-kernel quantize), f32 staging x2.
static constexpr int SB_OFF  = 0;                       // B: 3 * 128*144
static constexpr int AB_OFF  = 3 * 128 * AST;           // 55296; A: 2 * 64*144
static constexpr int STG_OFF = AB_OFF + 2 * 64 * AST;   // 73728; stg: 2 * 16384
static constexpr int SMEM2   = STG_OFF + 2 * 16384;     // 106496

__global__ void __launch_bounds__(128, 2) gemm2_fused(float* __restrict__ outp,
                                                      const float* __restrict__ bias)
{
    extern __shared__ __align__(16) unsigned char smem[];
    __shared__ float csc[128], cbd[128];

    const int tid = threadIdx.x, lane = tid & 31, wid = tid >> 5;
    const int warp_m = wid & 1, warp_n = wid >> 1;
    const int m0 = blockIdx.y * 64, n0 = blockIdx.x * 128;

    const float rs2 = __fdiv_rn(255.0f, fmaxf(g_maxh, EPSQ));
    {
        int n = n0 + tid;
        float s2 = __fdiv_rn(fmaxf(g_maxh, EPSQ), 255.0f);
        float sc = s2 * g_sw2[n];
        csc[tid] = sc;
        cbd[tid] = rintf(__fdiv_rn(bias[n], sc)) * sc;
    }

    const uint32_t sAddr = smem_u32(smem);
    const int NT = F_DIM / 64;   // 64

    auto loadB = [&](int t) {
        const uint32_t sb = sAddr + SB_OFF + (t % 3) * (128 * AST);
        const int kb = t * 64;
        #pragma unroll
        for (int it = 0; it < 8; ++it) {
            int i = tid + it * 128;
            int r = i >> 3, ch = i & 7;
            cp16(sb + r * AST + ch * 16, g_qw2 + (size_t)(n0 + r) * F_DIM + kb + ch * 8);
        }
    };
    auto loadAf = [&](int t) {
        const uint32_t sb = sAddr + STG_OFF + (t & 1) * 16384;
        const int kb = t * 64;
        #pragma unroll
        for (int it = 0; it < 8; ++it) {
            int i = tid + it * 128;
            int r = i >> 4, ch = i & 15;
            cp16(sb + r * 256 + ch * 16, g_h + (size_t)(m0 + r) * F_DIM + kb + ch * 4);
        }
    };
    auto quantA = [&](int t) {
        const int par = t & 1;
        #pragma unroll
        for (int it = 0; it < 8; ++it) {       // FIX: full 64-row coverage
            int i = tid + it * 128;
            int r = i >> 4, c4 = i & 15;
            float4 v = *reinterpret_cast<const float4*>(
                smem + STG_OFF + par * 16384 + r * 256 + c4 * 16);
            uint2 pk = quant_pack4(v, rs2, 0.0f, 255.0f);
            *reinterpret_cast<uint2*>(
                smem + AB_OFF + par * (64 * AST) + r * AST + c4 * 8) = pk;
        }
    };

    // prologue
    loadAf(0); loadB(0); CP_COMMIT();
    loadAf(1); loadB(1); CP_COMMIT();
    CP_WAIT1();
    __syncthreads();
    quantA(0);

    float acc[2][8][4];
    #pragma unroll
    for (int i = 0; i < 2; ++i)
        #pragma unroll
        for (int j = 0; j < 8; ++j)
            #pragma unroll
            for (int k = 0; k < 4; ++k) acc[i][j][k] = 0.0f;

    const uint32_t aLane =
        (uint32_t)(warp_m * 32 + (lane & 15)) * AST + (lane >> 4) * 16;
    const uint32_t bLane =
        (uint32_t)(warp_n * 64 + ((lane & 7) | ((lane & 16) >> 1))) * AST +
        ((lane >> 3) & 1) * 16;

    for (int t = 0; t < NT; ++t) {
        __syncthreads();                 // close iter t-1 (quantA(t)/compute done)
        if (t + 2 < NT) { loadAf(t + 2); loadB(t + 2); }
        CP_COMMIT();
        CP_WAIT1();                      // group(t+1) landed; group(t+2) in flight
        __syncthreads();                 // completion visible to all threads
        if (t + 1 < NT) quantA(t + 1);

        const uint32_t aBase = sAddr + AB_OFF + (t & 1) * (64 * AST);
        const uint32_t bBase = sAddr + SB_OFF + (t % 3) * (128 * AST);
        #pragma unroll
        for (int ks = 0; ks < 4; ++ks) {
            uint32_t af[2][4], bf[4][4];
            #pragma unroll
            for (int fm = 0; fm < 2; ++fm)
                ldsm4(af[fm], aBase + aLane + fm * (16 * AST) + ks * 32);
            #pragma unroll
            for (int fp = 0; fp < 4; ++fp)
                ldsm4(bf[fp], bBase + bLane + fp * (16 * AST) + ks * 32);
            #pragma unroll
            for (int fm = 0; fm < 2; ++fm)
                #pragma unroll
                for (int fn = 0; fn < 8; ++fn)
                    mma_bf16(acc[fm][fn], af[fm], &bf[fn >> 1][(fn & 1) * 2]);
        }
    }

    #pragma unroll
    for (int fm = 0; fm < 2; ++fm) {
        const int r0 = m0 + warp_m * 32 + fm * 16 + (lane >> 2);
        #pragma unroll
        for (int fn = 0; fn < 8; ++fn) {
            const int cl = warp_n * 64 + fn * 8 + (lane & 3) * 2;
            const float s0 = csc[cl], s1 = csc[cl + 1];
            const float d0 = cbd[cl], d1 = cbd[cl + 1];
            *reinterpret_cast<float2*>(outp + (size_t)r0 * D_DIM + n0 + cl) =
                make_float2(s0 * acc[fm][fn][0] + d0, s1 * acc[fm][fn][1] + d1);
            *reinterpret_cast<float2*>(outp + (size_t)(r0 + 8) * D_DIM + n0 + cl) =
                make_float2(s0 * acc[fm][fn][2] + d0, s1 * acc[fm][fn][3] + d1);
        }
    }
}

// ---------------- launcher ---------------------------------------------------
extern "C" void kernel_launch(void* const* d_in, const int* in_sizes, int n_in,
                              void* d_out, int out_size)
{
    const float* x  = (const float*)d_in[0];
    const float* w1 = (const float*)d_in[1];
    const float* b1 = (const float*)d_in[2];
    const float* w2 = (const float*)d_in[3];
    const float* b2 = (const float*)d_in[4];
    float* out = (float*)d_out;

    __nv_bfloat16* qw1p; cudaGetSymbolAddress((void**)&qw1p, g_qw1);
    __nv_bfloat16* qw2p; cudaGetSymbolAddress((void**)&qw2p, g_qw2);

    cudaFuncSetAttribute((const void*)gemm1_kernel,
                         cudaFuncAttributeMaxDynamicSharedMemorySize, SMEM1);
    cudaFuncSetAttribute((const void*)gemm2_fused,
                         cudaFuncAttributeMaxDynamicSharedMemorySize, SMEM2);

    max_x_kernel<<<SGRID, 256>>>(x);
    quantw_fused<D_DIM, true><<<F_DIM, 256>>>(w1, b1, qw1p);
    quantw_fused<F_DIM, false><<<D_DIM, 256>>>(w2, nullptr, qw2p);
    quant_x_kernel<<<SGRID, 256>>>(x);
    gemm1_kernel<<<dim3(F_DIM / 256, M_TOT / 128), 256, SMEM1>>>();
    gemm2_fused<<<dim3(D_DIM / 128, M_TOT / 64), 128, SMEM2>>>(out, b2);
}

// round 15
// speedup vs baseline: 1.2168x; 1.2168x over previous
#include <cuda_runtime.h>
#include <cuda_bf16.h>
#include <cstdint>
#include <cstddef>

// ============================================================================
// Quantized FFN via exact integer-in-bf16 GEMMs:
//   out = quant_linear(relu(quant_linear(x, w1, b1)), w2, b2)
// R15: R9 math restored (h in f32; bit-exact quantization). GEMM2 becomes a
// work-stealing persistent kernel (atomic tile queue) to kill its 4th-wave
// quantization tail. GEMM1 unchanged (at legacy-HMMA roofline).
// ============================================================================

#define EPSQ 1e-8f

static constexpr int M_TOT = 8192;
static constexpr int D_DIM = 1024;
static constexpr int F_DIM = 4096;
static constexpr int SGRID = 1184;

// ---------------- scratch ----------------------------------------------------
__device__ float g_maxx;
__device__ float g_maxh;
__device__ int   g_tile2;          // GEMM2 work-queue head (reset by quant_h)
__device__ __nv_bfloat16 g_qx[(size_t)M_TOT * D_DIM];
__device__ __nv_bfloat16 g_qw1[(size_t)F_DIM * D_DIM];
__device__ float g_scale1[F_DIM];
__device__ float g_badd1[F_DIM];
__device__ __nv_bfloat16 g_qw2[(size_t)D_DIM * F_DIM];
__device__ float g_sw2[D_DIM];
__device__ float g_h[(size_t)M_TOT * F_DIM];
__device__ __nv_bfloat16 g_qh[(size_t)M_TOT * F_DIM];

// ---------------- PTX helpers ------------------------------------------------
__device__ __forceinline__ uint32_t smem_u32(const void* p) {
    uint32_t a;
    asm("{ .reg .u64 t; cvta.to.shared.u64 t, %1; cvt.u32.u64 %0, t; }"
        : "=r"(a) : "l"(p));
    return a;
}

__device__ __forceinline__ void cp16(uint32_t dst, const void* src) {
    asm volatile("cp.async.cg.shared.global [%0], [%1], 16;" :: "r"(dst), "l"(src));
}
#define CP_COMMIT() asm volatile("cp.async.commit_group;" ::: "memory")
#define CP_WAIT2()  asm volatile("cp.async.wait_group 2;" ::: "memory")

__device__ __forceinline__ void ldsm4(uint32_t* r, uint32_t addr) {
    asm volatile("ldmatrix.sync.aligned.m8n8.x4.shared.b16 {%0,%1,%2,%3}, [%4];"
        : "=r"(r[0]), "=r"(r[1]), "=r"(r[2]), "=r"(r[3]) : "r"(addr));
}

__device__ __forceinline__ void mma_bf16(float* c, const uint32_t* a, const uint32_t* b) {
    asm volatile(
        "mma.sync.aligned.m16n8k16.row.col.f32.bf16.bf16.f32 "
        "{%0,%1,%2,%3}, {%4,%5,%6,%7}, {%8,%9}, {%0,%1,%2,%3};"
        : "+f"(c[0]), "+f"(c[1]), "+f"(c[2]), "+f"(c[3])
        : "r"(a[0]), "r"(a[1]), "r"(a[2]), "r"(a[3]), "r"(b[0]), "r"(b[1]));
}

__device__ __forceinline__ float4 ldcs4(const float4* p) {
    float4 v;
    asm volatile("ld.global.cs.v4.f32 {%0,%1,%2,%3}, [%4];"
        : "=f"(v.x), "=f"(v.y), "=f"(v.z), "=f"(v.w) : "l"(p));
    return v;
}

__device__ __forceinline__ uint2 quant_pack4(float4 v, float rs, float lo, float hi) {
    float q0 = fminf(fmaxf(rintf(v.x * rs), lo), hi);
    float q1 = fminf(fmaxf(rintf(v.y * rs), lo), hi);
    float q2 = fminf(fmaxf(rintf(v.z * rs), lo), hi);
    float q3 = fminf(fmaxf(rintf(v.w * rs), lo), hi);
    __nv_bfloat162 l = __floats2bfloat162_rn(q0, q1);
    __nv_bfloat162 h = __floats2bfloat162_rn(q2, q3);
    uint2 pk;
    pk.x = *reinterpret_cast<unsigned int*>(&l);
    pk.y = *reinterpret_cast<unsigned int*>(&h);
    return pk;
}

// ---------------- elementwise / reduction kernels ----------------------------
__global__ void max_x_kernel(const float* __restrict__ x) {
    float m = 0.0f;
    const int n4 = (M_TOT * D_DIM) / 4;
    const int stride = gridDim.x * blockDim.x;
    int i = blockIdx.x * blockDim.x + threadIdx.x;
    #pragma unroll 4
    for (; i < n4; i += stride) {
        float4 v = reinterpret_cast<const float4*>(x)[i];
        m = fmaxf(m, fmaxf(fmaxf(v.x, v.y), fmaxf(v.z, v.w)));
    }
    #pragma unroll
    for (int o = 16; o; o >>= 1) m = fmaxf(m, __shfl_xor_sync(0xffffffffu, m, o));
    __shared__ float red[8];
    int wid = threadIdx.x >> 5, lid = threadIdx.x & 31;
    if (lid == 0) red[wid] = m;
    __syncthreads();
    if (threadIdx.x == 0) {
        float b = red[0];
        int nw = blockDim.x >> 5;
        for (int i2 = 1; i2 < nw; i2++) b = fmaxf(b, red[i2]);
        atomicMax(reinterpret_cast<unsigned int*>(&g_maxx), __float_as_uint(fmaxf(b, 0.0f)));
    }
}

template <int K, bool W1>
__global__ void quantw_fused(const float* __restrict__ w, const float* __restrict__ b1,
                             __nv_bfloat16* __restrict__ qw) {
    constexpr int NV = K / 1024;
    const int r = blockIdx.x;
    const int t = threadIdx.x;
    const float4* row = reinterpret_cast<const float4*>(w + (size_t)r * K);
    float4 v[NV];
    float m = 0.0f;
    #pragma unroll
    for (int i = 0; i < NV; ++i) {
        v[i] = ldcs4(row + t + i * 256);
        m = fmaxf(m, fmaxf(fmaxf(fabsf(v[i].x), fabsf(v[i].y)),
                           fmaxf(fabsf(v[i].z), fabsf(v[i].w))));
    }
    #pragma unroll
    for (int o = 16; o; o >>= 1) m = fmaxf(m, __shfl_xor_sync(0xffffffffu, m, o));
    __shared__ float red[8];
    __shared__ float rs_sh;
    if ((t & 31) == 0) red[t >> 5] = m;
    __syncthreads();
    if (t == 0) {
        float b = red[0];
        #pragma unroll
        for (int i = 1; i < 8; ++i) b = fmaxf(b, red[i]);
        float s = __fdiv_rn(fmaxf(b, EPSQ), 127.0f);
        rs_sh = __fdiv_rn(1.0f, s);
        if (W1) {
            float s1 = __fdiv_rn(fmaxf(g_maxx, EPSQ), 255.0f);
            float sc = s1 * s;
            g_scale1[r] = sc;
            g_badd1[r] = rintf(__fdiv_rn(b1[r], sc)) * sc;
        } else {
            g_sw2[r] = s;
        }
    }
    __syncthreads();
    const float rs = rs_sh;
    #pragma unroll
    for (int i = 0; i < NV; ++i)
        reinterpret_cast<uint2*>(qw)[((size_t)r * K) / 4 + t + i * 256] =
            quant_pack4(v[i], rs, -128.0f, 127.0f);
}

__global__ void quant_x_kernel(const float* __restrict__ x) {
    const float rs = __fdiv_rn(255.0f, fmaxf(g_maxx, EPSQ));
    const int n4 = (M_TOT * D_DIM) / 4;
    const int stride = gridDim.x * blockDim.x;
    int i = blockIdx.x * blockDim.x + threadIdx.x;
    #pragma unroll 4
    for (; i < n4; i += stride) {
        float4 v = ldcs4(reinterpret_cast<const float4*>(x) + i);
        reinterpret_cast<uint2*>(g_qx)[i] = quant_pack4(v, rs, 0.0f, 255.0f);
    }
}

__global__ void quant_h_kernel() {
    if (blockIdx.x == 0 && threadIdx.x == 0) g_tile2 = 0;  // reset GEMM2 queue
    const float rs = __fdiv_rn(255.0f, fmaxf(g_maxh, EPSQ));
    const int n4 = (int)(((size_t)M_TOT * F_DIM) / 4);
    const int stride = gridDim.x * blockDim.x;
    int i = blockIdx.x * blockDim.x + threadIdx.x;
    #pragma unroll 8
    for (; i < n4; i += stride) {
        float4 v = ldcs4(reinterpret_cast<const float4*>(g_h) + i);
        reinterpret_cast<uint2*>(g_qh)[i] = quant_pack4(v, rs, 0.0f, 255.0f);
    }
}

// ---------------- GEMM1: qx x qw1 -> h (f32) + maxh --------------------------
// CTA 128x256x64; 256 thr, 8 warps 2(M)x4(N), warp 64x64; 4-stage cp.async.
static constexpr int AST = 144;
static constexpr int NSTAGE = 4;
static constexpr int STAGEB1 = (128 + 256) * AST;
static constexpr int SMEM1 = NSTAGE * STAGEB1;          // 221184

__global__ void __launch_bounds__(256, 1) gemm1_kernel()
{
    constexpr int ABYTES = 128 * AST;
    extern __shared__ __align__(16) unsigned char smem[];
    __shared__ float csc[256], cbd[256], wred[8];

    const int tid = threadIdx.x, lane = tid & 31, wid = tid >> 5;
    const int warp_m = wid & 1, warp_n = wid >> 1;
    const int m0 = blockIdx.y * 128, n0 = blockIdx.x * 256;

    {
        int n = n0 + tid;
        csc[tid] = g_scale1[n];
        cbd[tid] = g_badd1[n];
    }

    const uint32_t sAddr = smem_u32(smem);
    const int NT = D_DIM / 64;

    auto load_tile = [&](int t, int s) {
        const uint32_t sb = sAddr + s * STAGEB1;
        const int kb = t * 64;
        #pragma unroll
        for (int it = 0; it < 4; ++it) {
            int i = tid + it * 256;
            int r = i >> 3, ch = i & 7;
            cp16(sb + r * AST + ch * 16, g_qx + (size_t)(m0 + r) * D_DIM + kb + ch * 8);
        }
        #pragma unroll
        for (int it = 0; it < 8; ++it) {
            int i = tid + it * 256;
            int r = i >> 3, ch = i & 7;
            cp16(sb + ABYTES + r * AST + ch * 16,
                 g_qw1 + (size_t)(n0 + r) * D_DIM + kb + ch * 8);
        }
    };

    load_tile(0, 0); CP_COMMIT();
    load_tile(1, 1); CP_COMMIT();
    load_tile(2, 2); CP_COMMIT();

    float acc[4][8][4];
    #pragma unroll
    for (int i = 0; i < 4; ++i)
        #pragma unroll
        for (int j = 0; j < 8; ++j)
            #pragma unroll
            for (int k = 0; k < 4; ++k) acc[i][j][k] = 0.0f;

    const uint32_t aLane =
        (uint32_t)(warp_m * 64 + (lane & 15)) * AST + (lane >> 4) * 16;
    const uint32_t bLane = ABYTES +
        (uint32_t)(warp_n * 64 + ((lane & 7) | ((lane & 16) >> 1))) * AST +
        ((lane >> 3) & 1) * 16;

    int buf = 0;
    for (int t = 0; t < NT; ++t) {
        CP_WAIT2();
        __syncthreads();
        if (t + 3 < NT) {
            int s = buf + 3; if (s >= NSTAGE) s -= NSTAGE;
            load_tile(t + 3, s);
        }
        CP_COMMIT();

        const uint32_t base = sAddr + buf * STAGEB1;
        #pragma unroll
        for (int ks = 0; ks < 4; ++ks) {
            uint32_t af[4][4], bf[4][4];
            #pragma unroll
            for (int fm = 0; fm < 4; ++fm)
                ldsm4(af[fm], base + aLane + fm * (16 * AST) + ks * 32);
            #pragma unroll
            for (int fp = 0; fp < 4; ++fp)
                ldsm4(bf[fp], base + bLane + fp * (16 * AST) + ks * 32);
            #pragma unroll
            for (int fm = 0; fm < 4; ++fm)
                #pragma unroll
                for (int fn = 0; fn < 8; ++fn)
                    mma_bf16(acc[fm][fn], af[fm], &bf[fn >> 1][(fn & 1) * 2]);
        }
        if (++buf == NSTAGE) buf = 0;
    }

    float lmax = 0.0f;
    #pragma unroll
    for (int fm = 0; fm < 4; ++fm) {
        const int r0 = m0 + warp_m * 64 + fm * 16 + (lane >> 2);
        #pragma unroll
        for (int fn = 0; fn < 8; ++fn) {
            const int cl = warp_n * 64 + fn * 8 + (lane & 3) * 2;
            const float s0 = csc[cl], s1 = csc[cl + 1];
            const float d0 = cbd[cl], d1 = cbd[cl + 1];
            float v00 = fmaxf(s0 * acc[fm][fn][0] + d0, 0.0f);
            float v01 = fmaxf(s1 * acc[fm][fn][1] + d1, 0.0f);
            float v10 = fmaxf(s0 * acc[fm][fn][2] + d0, 0.0f);
            float v11 = fmaxf(s1 * acc[fm][fn][3] + d1, 0.0f);
            lmax = fmaxf(lmax, fmaxf(fmaxf(v00, v01), fmaxf(v10, v11)));
            *reinterpret_cast<float2*>(g_h + (size_t)r0 * F_DIM + n0 + cl) =
                make_float2(v00, v01);
            *reinterpret_cast<float2*>(g_h + (size_t)(r0 + 8) * F_DIM + n0 + cl) =
                make_float2(v10, v11);
        }
    }

    #pragma unroll
    for (int o = 16; o; o >>= 1) lmax = fmaxf(lmax, __shfl_xor_sync(0xffffffffu, lmax, o));
    if (lane == 0) wred[wid] = lmax;
    __syncthreads();
    if (tid == 0) {
        float b = wred[0];
        #pragma unroll
        for (int i = 1; i < 8; i++) b = fmaxf(b, wred[i]);
        atomicMax(reinterpret_cast<unsigned int*>(&g_maxh), __float_as_uint(b));
    }
}

// ---------------- GEMM2: persistent work-stealing, qh x qw2 -> out -----------
// Tile 64x128x64; 128 thr, 4 warps 2(M)x2(N), warp 32x64; 2 CTAs/SM.
// 1024 tiles pulled from an atomic queue (reset by quant_h each launch).
static constexpr int NTILES2 = (M_TOT / 64) * (D_DIM / 128);   // 1024
static constexpr int STAGEB2 = (64 + 128) * AST;               // 27648
static constexpr int SMEM2 = NSTAGE * STAGEB2;                 // 110592
static constexpr int GRID2 = 304;                              // 2 x 152 SMs

__global__ void __launch_bounds__(128, 2) gemm2_persist(float* __restrict__ outp,
                                                        const float* __restrict__ bias)
{
    constexpr int ABYTES = 64 * AST;
    extern __shared__ __align__(16) unsigned char smem[];
    __shared__ float csc[128], cbd[128];
    __shared__ int s_tile;

    const int tid = threadIdx.x, lane = tid & 31, wid = tid >> 5;
    const int warp_m = wid & 1, warp_n = wid >> 1;
    const float s2 = __fdiv_rn(fmaxf(g_maxh, EPSQ), 255.0f);

    const uint32_t sAddr = smem_u32(smem);
    const int NT = F_DIM / 64;   // 64

    const uint32_t aLane =
        (uint32_t)(warp_m * 32 + (lane & 15)) * AST + (lane >> 4) * 16;
    const uint32_t bLane = ABYTES +
        (uint32_t)(warp_n * 64 + ((lane & 7) | ((lane & 16) >> 1))) * AST +
        ((lane >> 3) & 1) * 16;

    while (true) {
        if (tid == 0) s_tile = atomicAdd(&g_tile2, 1);
        __syncthreads();                       // also closes previous epilogue
        const int tile = s_tile;
        if (tile >= NTILES2) break;
        const int m0 = (tile >> 3) * 64;       // 128 m-slabs
        const int n0 = (tile & 7) * 128;       // 8 n-slabs

        {
            int n = n0 + tid;
            float sc = s2 * g_sw2[n];
            csc[tid] = sc;
            cbd[tid] = rintf(__fdiv_rn(bias[n], sc)) * sc;
        }

        auto load_tile = [&](int t, int s) {
            const uint32_t sb = sAddr + s * STAGEB2;
            const int kb = t * 64;
            #pragma unroll
            for (int it = 0; it < 4; ++it) {
                int i = tid + it * 128;
                int r = i >> 3, ch = i & 7;
                cp16(sb + r * AST + ch * 16,
                     g_qh + (size_t)(m0 + r) * F_DIM + kb + ch * 8);
            }
            #pragma unroll
            for (int it = 0; it < 8; ++it) {
                int i = tid + it * 128;
                int r = i >> 3, ch = i & 7;
                cp16(sb + ABYTES + r * AST + ch * 16,
                     g_qw2 + (size_t)(n0 + r) * F_DIM + kb + ch * 8);
            }
        };

        load_tile(0, 0); CP_COMMIT();
        load_tile(1, 1); CP_COMMIT();
        load_tile(2, 2); CP_COMMIT();

        float acc[2][8][4];
        #pragma unroll
        for (int i = 0; i < 2; ++i)
            #pragma unroll
            for (int j = 0; j < 8; ++j)
                #pragma unroll
                for (int k = 0; k < 4; ++k) acc[i][j][k] = 0.0f;

        int buf = 0;
        for (int t = 0; t < NT; ++t) {
            CP_WAIT2();
            __syncthreads();
            if (t + 3 < NT) {
                int s = buf + 3; if (s >= NSTAGE) s -= NSTAGE;
                load_tile(t + 3, s);
            }
            CP_COMMIT();

            const uint32_t base = sAddr + buf * STAGEB2;
            #pragma unroll
            for (int ks = 0; ks < 4; ++ks) {
                uint32_t af[2][4], bf[4][4];
                #pragma unroll
                for (int fm = 0; fm < 2; ++fm)
                    ldsm4(af[fm], base + aLane + fm * (16 * AST) + ks * 32);
                #pragma unroll
                for (int fp = 0; fp < 4; ++fp)
                    ldsm4(bf[fp], base + bLane + fp * (16 * AST) + ks * 32);
                #pragma unroll
                for (int fm = 0; fm < 2; ++fm)
                    #pragma unroll
                    for (int fn = 0; fn < 8; ++fn)
                        mma_bf16(acc[fm][fn], af[fm], &bf[fn >> 1][(fn & 1) * 2]);
            }
            if (++buf == NSTAGE) buf = 0;
        }

        #pragma unroll
        for (int fm = 0; fm < 2; ++fm) {
            const int r0 = m0 + warp_m * 32 + fm * 16 + (lane >> 2);
            #pragma unroll
            for (int fn = 0; fn < 8; ++fn) {
                const int cl = warp_n * 64 + fn * 8 + (lane & 3) * 2;
                const float s0 = csc[cl], s1 = csc[cl + 1];
                const float d0 = cbd[cl], d1 = cbd[cl + 1];
                *reinterpret_cast<float2*>(outp + (size_t)r0 * D_DIM + n0 + cl) =
                    make_float2(s0 * acc[fm][fn][0] + d0, s1 * acc[fm][fn][1] + d1);
                *reinterpret_cast<float2*>(outp + (size_t)(r0 + 8) * D_DIM + n0 + cl) =
                    make_float2(s0 * acc[fm][fn][2] + d0, s1 * acc[fm][fn][3] + d1);
            }
        }
    }
}

// ---------------- launcher ---------------------------------------------------
extern "C" void kernel_launch(void* const* d_in, const int* in_sizes, int n_in,
                              void* d_out, int out_size)
{
    const float* x  = (const float*)d_in[0];
    const float* w1 = (const float*)d_in[1];
    const float* b1 = (const float*)d_in[2];
    const float* w2 = (const float*)d_in[3];
    const float* b2 = (const float*)d_in[4];
    float* out = (float*)d_out;

    __nv_bfloat16* qw1p; cudaGetSymbolAddress((void**)&qw1p, g_qw1);
    __nv_bfloat16* qw2p; cudaGetSymbolAddress((void**)&qw2p, g_qw2);

    cudaFuncSetAttribute((const void*)gemm1_kernel,
                         cudaFuncAttributeMaxDynamicSharedMemorySize, SMEM1);
    cudaFuncSetAttribute((const void*)gemm2_persist,
                         cudaFuncAttributeMaxDynamicSharedMemorySize, SMEM2);

    max_x_kernel<<<SGRID, 256>>>(x);
    quantw_fused<D_DIM, true><<<F_DIM, 256>>>(w1, b1, qw1p);
    quantw_fused<F_DIM, false><<<D_DIM, 256>>>(w2, nullptr, qw2p);
    quant_x_kernel<<<SGRID, 256>>>(x);
    gemm1_kernel<<<dim3(F_DIM / 256, M_TOT / 128), 256, SMEM1>>>();
    quant_h_kernel<<<SGRID, 256>>>();
    gemm2_persist<<<GRID2, 128, SMEM2>>>(out, b2);
}

// round 16
// speedup vs baseline: 1.2543x; 1.0308x over previous
#include <cuda_runtime.h>
#include <cuda_bf16.h>
#include <cstdint>
#include <cstddef>

// ============================================================================
// Quantized FFN via exact integer-in-bf16 GEMMs:
//   out = quant_linear(relu(quant_linear(x, w1, b1)), w2, b2)
// R16: exact R9 structure (the measured optimum: GEMMs at the legacy-HMMA
// quarter-rate roofline, h in f32, split quant_h) + merged weight-quant launch.
// ============================================================================

#define EPSQ 1e-8f

static constexpr int M_TOT = 8192;
static constexpr int D_DIM = 1024;
static constexpr int F_DIM = 4096;
static constexpr int SGRID = 1184;

// ---------------- scratch ----------------------------------------------------
__device__ float g_maxx;
__device__ float g_maxh;
__device__ __nv_bfloat16 g_qx[(size_t)M_TOT * D_DIM];
__device__ __nv_bfloat16 g_qw1[(size_t)F_DIM * D_DIM];
__device__ float g_scale1[F_DIM];
__device__ float g_badd1[F_DIM];
__device__ __nv_bfloat16 g_qw2[(size_t)D_DIM * F_DIM];
__device__ float g_sw2[D_DIM];
__device__ float g_h[(size_t)M_TOT * F_DIM];
__device__ __nv_bfloat16 g_qh[(size_t)M_TOT * F_DIM];

// ---------------- PTX helpers ------------------------------------------------
__device__ __forceinline__ uint32_t smem_u32(const void* p) {
    uint32_t a;
    asm("{ .reg .u64 t; cvta.to.shared.u64 t, %1; cvt.u32.u64 %0, t; }"
        : "=r"(a) : "l"(p));
    return a;
}

__device__ __forceinline__ void cp16(uint32_t dst, const void* src) {
    asm volatile("cp.async.cg.shared.global [%0], [%1], 16;" :: "r"(dst), "l"(src));
}
#define CP_COMMIT() asm volatile("cp.async.commit_group;" ::: "memory")
#define CP_WAIT2()  asm volatile("cp.async.wait_group 2;" ::: "memory")

__device__ __forceinline__ void ldsm4(uint32_t* r, uint32_t addr) {
    asm volatile("ldmatrix.sync.aligned.m8n8.x4.shared.b16 {%0,%1,%2,%3}, [%4];"
        : "=r"(r[0]), "=r"(r[1]), "=r"(r[2]), "=r"(r[3]) : "r"(addr));
}

__device__ __forceinline__ void mma_bf16(float* c, const uint32_t* a, const uint32_t* b) {
    asm volatile(
        "mma.sync.aligned.m16n8k16.row.col.f32.bf16.bf16.f32 "
        "{%0,%1,%2,%3}, {%4,%5,%6,%7}, {%8,%9}, {%0,%1,%2,%3};"
        : "+f"(c[0]), "+f"(c[1]), "+f"(c[2]), "+f"(c[3])
        : "r"(a[0]), "r"(a[1]), "r"(a[2]), "r"(a[3]), "r"(b[0]), "r"(b[1]));
}

__device__ __forceinline__ float4 ldcs4(const float4* p) {
    float4 v;
    asm volatile("ld.global.cs.v4.f32 {%0,%1,%2,%3}, [%4];"
        : "=f"(v.x), "=f"(v.y), "=f"(v.z), "=f"(v.w) : "l"(p));
    return v;
}

__device__ __forceinline__ uint2 quant_pack4(float4 v, float rs, float lo, float hi) {
    float q0 = fminf(fmaxf(rintf(v.x * rs), lo), hi);
    float q1 = fminf(fmaxf(rintf(v.y * rs), lo), hi);
    float q2 = fminf(fmaxf(rintf(v.z * rs), lo), hi);
    float q3 = fminf(fmaxf(rintf(v.w * rs), lo), hi);
    __nv_bfloat162 l = __floats2bfloat162_rn(q0, q1);
    __nv_bfloat162 h = __floats2bfloat162_rn(q2, q3);
    uint2 pk;
    pk.x = *reinterpret_cast<unsigned int*>(&l);
    pk.y = *reinterpret_cast<unsigned int*>(&h);
    return pk;
}

// ---------------- elementwise / reduction kernels ----------------------------
__global__ void max_x_kernel(const float* __restrict__ x) {
    float m = 0.0f;
    const int n4 = (M_TOT * D_DIM) / 4;
    const int stride = gridDim.x * blockDim.x;
    int i = blockIdx.x * blockDim.x + threadIdx.x;
    #pragma unroll 4
    for (; i < n4; i += stride) {
        float4 v = reinterpret_cast<const float4*>(x)[i];
        m = fmaxf(m, fmaxf(fmaxf(v.x, v.y), fmaxf(v.z, v.w)));
    }
    #pragma unroll
    for (int o = 16; o; o >>= 1) m = fmaxf(m, __shfl_xor_sync(0xffffffffu, m, o));
    __shared__ float red[8];
    int wid = threadIdx.x >> 5, lid = threadIdx.x & 31;
    if (lid == 0) red[wid] = m;
    __syncthreads();
    if (threadIdx.x == 0) {
        float b = red[0];
        int nw = blockDim.x >> 5;
        for (int i2 = 1; i2 < nw; i2++) b = fmaxf(b, red[i2]);
        atomicMax(reinterpret_cast<unsigned int*>(&g_maxx), __float_as_uint(fmaxf(b, 0.0f)));
    }
}

// one row of a [R, K] weight: per-row |max| scale + quantize (row in registers)
template <int K, bool W1>
__device__ __forceinline__ void quantw_row(int r, const float* __restrict__ w,
                                           const float* __restrict__ b1,
                                           __nv_bfloat16* __restrict__ qw) {
    constexpr int NV = K / 1024;
    const int t = threadIdx.x;
    const float4* row = reinterpret_cast<const float4*>(w + (size_t)r * K);
    float4 v[NV];
    float m = 0.0f;
    #pragma unroll
    for (int i = 0; i < NV; ++i) {
        v[i] = ldcs4(row + t + i * 256);
        m = fmaxf(m, fmaxf(fmaxf(fabsf(v[i].x), fabsf(v[i].y)),
                           fmaxf(fabsf(v[i].z), fabsf(v[i].w))));
    }
    #pragma unroll
    for (int o = 16; o; o >>= 1) m = fmaxf(m, __shfl_xor_sync(0xffffffffu, m, o));
    __shared__ float red[8];
    __shared__ float rs_sh;
    if ((t & 31) == 0) red[t >> 5] = m;
    __syncthreads();
    if (t == 0) {
        float b = red[0];
        #pragma unroll
        for (int i = 1; i < 8; ++i) b = fmaxf(b, red[i]);
        float s = __fdiv_rn(fmaxf(b, EPSQ), 127.0f);
        rs_sh = __fdiv_rn(1.0f, s);
        if (W1) {
            float s1 = __fdiv_rn(fmaxf(g_maxx, EPSQ), 255.0f);
            float sc = s1 * s;
            g_scale1[r] = sc;
            g_badd1[r] = rintf(__fdiv_rn(b1[r], sc)) * sc;
        } else {
            g_sw2[r] = s;
        }
    }
    __syncthreads();
    const float rs = rs_sh;
    #pragma unroll
    for (int i = 0; i < NV; ++i)
        reinterpret_cast<uint2*>(qw)[((size_t)r * K) / 4 + t + i * 256] =
            quant_pack4(v[i], rs, -128.0f, 127.0f);
}

// merged weight quantization: blocks [0, F_DIM) -> w1 rows; rest -> w2 rows
__global__ void quantw_all(const float* __restrict__ w1, const float* __restrict__ b1,
                           const float* __restrict__ w2,
                           __nv_bfloat16* __restrict__ qw1,
                           __nv_bfloat16* __restrict__ qw2) {
    if (blockIdx.x < F_DIM)
        quantw_row<D_DIM, true>(blockIdx.x, w1, b1, qw1);
    else
        quantw_row<F_DIM, false>(blockIdx.x - F_DIM, w2, nullptr, qw2);
}

__global__ void quant_x_kernel(const float* __restrict__ x) {
    const float rs = __fdiv_rn(255.0f, fmaxf(g_maxx, EPSQ));
    const int n4 = (M_TOT * D_DIM) / 4;
    const int stride = gridDim.x * blockDim.x;
    int i = blockIdx.x * blockDim.x + threadIdx.x;
    #pragma unroll 4
    for (; i < n4; i += stride) {
        float4 v = ldcs4(reinterpret_cast<const float4*>(x) + i);
        reinterpret_cast<uint2*>(g_qx)[i] = quant_pack4(v, rs, 0.0f, 255.0f);
    }
}

__global__ void quant_h_kernel() {
    const float rs = __fdiv_rn(255.0f, fmaxf(g_maxh, EPSQ));
    const int n4 = (int)(((size_t)M_TOT * F_DIM) / 4);
    const int stride = gridDim.x * blockDim.x;
    int i = blockIdx.x * blockDim.x + threadIdx.x;
    #pragma unroll 8
    for (; i < n4; i += stride) {
        float4 v = ldcs4(reinterpret_cast<const float4*>(g_h) + i);
        reinterpret_cast<uint2*>(g_qh)[i] = quant_pack4(v, rs, 0.0f, 255.0f);
    }
}

// ---------------- bf16 GEMM (generalized tile) -------------------------------
// D[m,n] = sum_k A[m,k]*B[n,k]; mma m16n8k16 bf16->f32; ldmatrix.x4;
// 4-stage cp.async, one __syncthreads per K-tile.
// G1 : 128x256 CTA, 256 thr, 8 warps 2(M)x4(N), warp 64x64, 1 CTA/SM.
// !G1:  64x128 CTA, 128 thr, 4 warps 2(M)x2(N), warp 32x64, 2 CTAs/SM.
static constexpr int AST = 144;
static constexpr int NSTAGE = 4;

template <int KTOT, int NTOT, int TMp, int TNp, int WM, int THREADS, int MINB, bool G1>
__global__ void __launch_bounds__(THREADS, MINB)
gemm_hmma(float* __restrict__ outp, const float* __restrict__ bias)
{
    constexpr int ABYTES = TMp * AST;
    constexpr int STAGEB = (TMp + TNp) * AST;
    constexpr int NWM = TMp / WM;
    constexpr int FM = WM / 16;
    constexpr int AIT = TMp * 8 / THREADS;
    constexpr int BIT = TNp * 8 / THREADS;

    extern __shared__ __align__(16) unsigned char smem[];
    __shared__ float csc[TNp], cbd[TNp], wred[THREADS / 32];

    const int tid = threadIdx.x, lane = tid & 31, wid = tid >> 5;
    const int warp_m = wid % NWM, warp_n = wid / NWM;
    const int m0 = blockIdx.y * TMp, n0 = blockIdx.x * TNp;

    const __nv_bfloat16* __restrict__ A = G1 ? g_qx : g_qh;
    const __nv_bfloat16* __restrict__ B = G1 ? g_qw1 : g_qw2;

    if (tid < TNp) {
        int n = n0 + tid;
        if (G1) {
            csc[tid] = g_scale1[n];
            cbd[tid] = g_badd1[n];
        } else {
            float s2 = __fdiv_rn(fmaxf(g_maxh, EPSQ), 255.0f);
            float sc = s2 * g_sw2[n];
            csc[tid] = sc;
            cbd[tid] = rintf(__fdiv_rn(bias[n], sc)) * sc;
        }
    }

    const uint32_t sAddr = smem_u32(smem);
    const int NT = KTOT / 64;

    auto load_tile = [&](int t, int s) {
        const uint32_t sb = sAddr + s * STAGEB;
        const int kb = t * 64;
        #pragma unroll
        for (int it = 0; it < AIT; ++it) {
            int i = tid + it * THREADS;
            int r = i >> 3, ch = i & 7;
            cp16(sb + r * AST + ch * 16, A + (size_t)(m0 + r) * KTOT + kb + ch * 8);
        }
        #pragma unroll
        for (int it = 0; it < BIT; ++it) {
            int i = tid + it * THREADS;
            int r = i >> 3, ch = i & 7;
            cp16(sb + ABYTES + r * AST + ch * 16, B + (size_t)(n0 + r) * KTOT + kb + ch * 8);
        }
    };

    load_tile(0, 0); CP_COMMIT();
    load_tile(1, 1); CP_COMMIT();
    load_tile(2, 2); CP_COMMIT();

    float acc[FM][8][4];
    #pragma unroll
    for (int i = 0; i < FM; ++i)
        #pragma unroll
        for (int j = 0; j < 8; ++j)
            #pragma unroll
            for (int k = 0; k < 4; ++k) acc[i][j][k] = 0.0f;

    const uint32_t aLane =
        (uint32_t)(warp_m * WM + (lane & 15)) * AST + (lane >> 4) * 16;
    const uint32_t bLane = ABYTES +
        (uint32_t)(warp_n * 64 + ((lane & 7) | ((lane & 16) >> 1))) * AST +
        ((lane >> 3) & 1) * 16;

    int buf = 0;
    for (int t = 0; t < NT; ++t) {
        CP_WAIT2();
        __syncthreads();
        if (t + 3 < NT) {
            int s = buf + 3; if (s >= NSTAGE) s -= NSTAGE;
            load_tile(t + 3, s);
        }
        CP_COMMIT();

        const uint32_t base = sAddr + buf * STAGEB;
        #pragma unroll
        for (int ks = 0; ks < 4; ++ks) {
            uint32_t af[FM][4], bf[4][4];
            #pragma unroll
            for (int fm = 0; fm < FM; ++fm)
                ldsm4(af[fm], base + aLane + fm * (16 * AST) + ks * 32);
            #pragma unroll
            for (int fp = 0; fp < 4; ++fp)
                ldsm4(bf[fp], base + bLane + fp * (16 * AST) + ks * 32);
            #pragma unroll
            for (int fm = 0; fm < FM; ++fm)
                #pragma unroll
                for (int fn = 0; fn < 8; ++fn)
                    mma_bf16(acc[fm][fn], af[fm], &bf[fn >> 1][(fn & 1) * 2]);
        }
        if (++buf == NSTAGE) buf = 0;
    }

    // -------- epilogue -------------------------------------------------------
    float* __restrict__ O = G1 ? g_h : outp;
    float lmax = 0.0f;
    #pragma unroll
    for (int fm = 0; fm < FM; ++fm) {
        const int r0 = m0 + warp_m * WM + fm * 16 + (lane >> 2);
        #pragma unroll
        for (int fn = 0; fn < 8; ++fn) {
            const int cl = warp_n * 64 + fn * 8 + (lane & 3) * 2;
            const float s0 = csc[cl], s1 = csc[cl + 1];
            const float d0 = cbd[cl], d1 = cbd[cl + 1];
            float v00 = s0 * acc[fm][fn][0] + d0;
            float v01 = s1 * acc[fm][fn][1] + d1;
            float v10 = s0 * acc[fm][fn][2] + d0;
            float v11 = s1 * acc[fm][fn][3] + d1;
            if (G1) {
                v00 = fmaxf(v00, 0.0f); v01 = fmaxf(v01, 0.0f);
                v10 = fmaxf(v10, 0.0f); v11 = fmaxf(v11, 0.0f);
                lmax = fmaxf(lmax, fmaxf(fmaxf(v00, v01), fmaxf(v10, v11)));
            }
            *reinterpret_cast<float2*>(O + (size_t)r0 * NTOT + n0 + cl) =
                make_float2(v00, v01);
            *reinterpret_cast<float2*>(O + (size_t)(r0 + 8) * NTOT + n0 + cl) =
                make_float2(v10, v11);
        }
    }

    if (G1) {
        #pragma unroll
        for (int o = 16; o; o >>= 1) lmax = fmaxf(lmax, __shfl_xor_sync(0xffffffffu, lmax, o));
        if (lane == 0) wred[wid] = lmax;
        __syncthreads();
        if (tid == 0) {
            float b = wred[0];
            #pragma unroll
            for (int i = 1; i < THREADS / 32; i++) b = fmaxf(b, wred[i]);
            atomicMax(reinterpret_cast<unsigned int*>(&g_maxh), __float_as_uint(b));
        }
    }
}

// ---------------- launcher ---------------------------------------------------
extern "C" void kernel_launch(void* const* d_in, const int* in_sizes, int n_in,
                              void* d_out, int out_size)
{
    const float* x  = (const float*)d_in[0];
    const float* w1 = (const float*)d_in[1];
    const float* b1 = (const float*)d_in[2];
    const float* w2 = (const float*)d_in[3];
    const float* b2 = (const float*)d_in[4];
    float* out = (float*)d_out;

    __nv_bfloat16* qw1p; cudaGetSymbolAddress((void**)&qw1p, g_qw1);
    __nv_bfloat16* qw2p; cudaGetSymbolAddress((void**)&qw2p, g_qw2);

    constexpr int SMEM1 = NSTAGE * (128 + 256) * AST;   // 221184
    constexpr int SMEM2 = NSTAGE * (64 + 128) * AST;    // 110592

    auto k1 = gemm_hmma<D_DIM, F_DIM, 128, 256, 64, 256, 1, true>;
    auto k2 = gemm_hmma<F_DIM, D_DIM, 64, 128, 32, 128, 2, false>;
    cudaFuncSetAttribute((const void*)k1, cudaFuncAttributeMaxDynamicSharedMemorySize, SMEM1);
    cudaFuncSetAttribute((const void*)k2, cudaFuncAttributeMaxDynamicSharedMemorySize, SMEM2);

    max_x_kernel<<<SGRID, 256>>>(x);
    quantw_all<<<F_DIM + D_DIM, 256>>>(w1, b1, w2, qw1p, qw2p);
    quant_x_kernel<<<SGRID, 256>>>(x);
    k1<<<dim3(F_DIM / 256, M_TOT / 128), 256, SMEM1>>>(nullptr, nullptr);
    quant_h_kernel<<<SGRID, 256>>>();
    k2<<<dim3(D_DIM / 128, M_TOT / 64), 128, SMEM2>>>(out, b2);
}